// round 4
// baseline (speedup 1.0000x reference)
#include <cuda_runtime.h>

// ---------------------------------------------------------------------------
// ClockAwareGNN fused kernel set.
//
// Math reduction:
//   graph_pred[g]   = (sum_{n in g} dot(x[n], W_base)) / cnt_g + b_base
//   clock_pooled[g] = (sum_{n in g} relu(c_n * W1 + b1)) / cnt_g @ W2 + b2
//   out[g]          = relu([graph_pred, clock_pooled] @ W3 + b3) @ W4 + b4
//
// So the streaming pass only accumulates 18 floats per graph:
//   slots 0..15 : sum of r = relu(c*W1+b1)    (16-vector)
//   slot  16    : sum of s = dot(x_row, W_base)
//   slot  17    : node count
// ---------------------------------------------------------------------------

#define HID 16
#define ACC_STRIDE 18
#define MAX_GRAPHS 4096

__device__ float g_acc[MAX_GRAPHS * ACC_STRIDE];

// ---------------------------------------------------------------------------
__global__ void zero_acc_kernel(int total) {
    int i = blockIdx.x * blockDim.x + threadIdx.x;
    if (i < total) g_acc[i] = 0.0f;
}

// ---------------------------------------------------------------------------
// One warp processes a contiguous chunk of node rows. batch[] is sorted, so
// the graph id is piecewise-constant over the chunk: accumulate in registers,
// flush with atomics only when the graph id changes (or at chunk end).
//
// Lane l loads float4 l of the 128-float row  -> coalesced 512B per warp-node.
// Lanes 0..15 additionally own one component of the r accumulator.
// ---------------------------------------------------------------------------
__global__ __launch_bounds__(256) void accum_kernel(
    const float4* __restrict__ x4,      // [N, 32] float4 view of x[N,128]
    const float*  __restrict__ clockp,  // [N]
    const int*    __restrict__ batch,   // [N] sorted
    const float4* __restrict__ Wb4,     // [32] float4 view of W_base[128]
    const float*  __restrict__ W1,      // [16]
    const float*  __restrict__ b1,      // [16]
    int N, int chunk)
{
    const int lane = threadIdx.x & 31;
    const int gwid = (blockIdx.x * blockDim.x + threadIdx.x) >> 5;

    int start = gwid * chunk;
    if (start >= N) return;
    int end = start + chunk;
    if (end > N) end = N;

    const float4 wb = Wb4[lane];
    float w1l = 0.0f, b1l = -1.0f;
    if (lane < HID) { w1l = W1[lane]; b1l = b1[lane]; }

    int   cur   = batch[start];
    float pacc0 = 0.0f, pacc1 = 0.0f;   // split dot chains (ILP)
    float racc  = 0.0f;
    float cnt   = 0.0f;

    for (int n = start; n < end; ++n) {
        // issue streaming loads first (independent of the flush branch)
        const float4 xv = x4[(n << 5) + lane];
        const int    g  = batch[n];     // broadcast, L1-resident 7/8 iters
        const float  c  = clockp[n];    // broadcast

        if (g != cur) {
            // flush current graph's accumulators
            float s = pacc0 + pacc1;
            #pragma unroll
            for (int off = 16; off; off >>= 1)
                s += __shfl_xor_sync(0xffffffffu, s, off);
            if (lane < HID)        atomicAdd(&g_acc[cur * ACC_STRIDE + lane], racc);
            else if (lane == HID)  atomicAdd(&g_acc[cur * ACC_STRIDE + 16],  s);
            else if (lane == HID+1)atomicAdd(&g_acc[cur * ACC_STRIDE + 17],  cnt);
            pacc0 = 0.0f; pacc1 = 0.0f; racc = 0.0f; cnt = 0.0f;
            cur = g;
        }

        pacc0 = fmaf(xv.x, wb.x, pacc0);
        pacc1 = fmaf(xv.y, wb.y, pacc1);
        pacc0 = fmaf(xv.z, wb.z, pacc0);
        pacc1 = fmaf(xv.w, wb.w, pacc1);
        if (lane < HID) racc += fmaxf(fmaf(c, w1l, b1l), 0.0f);
        cnt += 1.0f;
    }

    // final flush
    {
        float s = pacc0 + pacc1;
        #pragma unroll
        for (int off = 16; off; off >>= 1)
            s += __shfl_xor_sync(0xffffffffu, s, off);
        if (lane < HID)         atomicAdd(&g_acc[cur * ACC_STRIDE + lane], racc);
        else if (lane == HID)   atomicAdd(&g_acc[cur * ACC_STRIDE + 16],  s);
        else if (lane == HID+1) atomicAdd(&g_acc[cur * ACC_STRIDE + 17],  cnt);
    }
}

// ---------------------------------------------------------------------------
// Final per-graph MLP. One thread per graph; weights are tiny and L1/L2-hot.
// ---------------------------------------------------------------------------
__global__ __launch_bounds__(256) void final_kernel(
    const float* __restrict__ b_base,   // [1]
    const float* __restrict__ W2,       // [16,16] row-major
    const float* __restrict__ b2,       // [16]
    const float* __restrict__ W3,       // [17,32] row-major
    const float* __restrict__ b3,       // [32]
    const float* __restrict__ W4,       // [32]
    const float* __restrict__ b4,       // [1]
    float* __restrict__ out,            // [B]
    int B)
{
    int g = blockIdx.x * blockDim.x + threadIdx.x;
    if (g >= B) return;

    const float* a = &g_acc[g * ACC_STRIDE];
    float cnt   = a[17];
    float inv   = 1.0f / fmaxf(cnt, 1.0f);

    float combined[HID + 1];
    combined[0] = a[16] * inv + b_base[0];

    float mr[HID];
    #pragma unroll
    for (int i = 0; i < HID; ++i) mr[i] = a[i] * inv;

    #pragma unroll
    for (int j = 0; j < HID; ++j) {
        float v = b2[j];
        #pragma unroll
        for (int i = 0; i < HID; ++i)
            v = fmaf(mr[i], W2[i * HID + j], v);
        combined[1 + j] = v;
    }

    float o = b4[0];
    #pragma unroll
    for (int k = 0; k < 32; ++k) {
        float h = b3[k];
        #pragma unroll
        for (int t = 0; t < HID + 1; ++t)
            h = fmaf(combined[t], W3[t * 32 + k], h);
        o = fmaf(fmaxf(h, 0.0f), W4[k], o);
    }
    out[g] = o;
}

// ---------------------------------------------------------------------------
extern "C" void kernel_launch(void* const* d_in, const int* in_sizes, int n_in,
                              void* d_out, int out_size)
{
    // metadata order: x, clock_period, batch, W_base, b_base, W1, b1, W2, b2,
    //                 W3, b3, W4, b4
    const float* x       = (const float*)d_in[0];
    const float* clockp  = (const float*)d_in[1];
    const int*   batch   = (const int*)  d_in[2];
    const float* W_base  = (const float*)d_in[3];
    const float* b_base  = (const float*)d_in[4];
    const float* W1      = (const float*)d_in[5];
    const float* b1      = (const float*)d_in[6];
    const float* W2      = (const float*)d_in[7];
    const float* b2      = (const float*)d_in[8];
    const float* W3      = (const float*)d_in[9];
    const float* b3      = (const float*)d_in[10];
    const float* W4      = (const float*)d_in[11];
    const float* b4      = (const float*)d_in[12];
    float*       out     = (float*)d_out;

    const int N = in_sizes[2];          // number of nodes (batch length)
    const int B = out_size;             // number of graphs

    // 1) zero the per-graph accumulators
    {
        int total = B * ACC_STRIDE;
        int blk = 256;
        zero_acc_kernel<<<(total + blk - 1) / blk, blk>>>(total);
    }

    // 2) streaming accumulation: 8 blocks/SM * 148 SMs, 256 threads each
    {
        const int BLK = 256;
        const int GRID = 148 * 8;
        const int warps = GRID * (BLK / 32);
        int chunk = (N + warps - 1) / warps;
        accum_kernel<<<GRID, BLK>>>(
            (const float4*)x, clockp, batch, (const float4*)W_base,
            W1, b1, N, chunk);
    }

    // 3) per-graph final MLP
    {
        int blk = 256;
        final_kernel<<<(B + blk - 1) / blk, blk>>>(
            b_base, W2, b2, W3, b3, W4, b4, out, B);
    }
}

// round 7
// speedup vs baseline: 1.0002x; 1.0002x over previous
#include <cuda_runtime.h>

// ---------------------------------------------------------------------------
// ClockAwareGNN fused kernel set (round 4).
//
// Math reduction:
//   graph_pred[g]   = (sum_{n in g} dot(x[n], W_base)) / cnt_g + b_base
//   clock_pooled[g] = (sum_{n in g} relu(c_n * W1 + b1)) / cnt_g @ W2 + b2
//   out[g]          = relu([graph_pred, clock_pooled] @ W3 + b3) @ W4 + b4
//
// Streaming pass accumulates 18 floats per graph:
//   slots 0..15 : sum of r = relu(c*W1+b1)
//   slot  16    : sum of s = dot(x_row, W_base)
//   slot  17    : node count
//
// g_acc invariant: zero at every kernel_launch entry. It is zero-initialized
// at module load, and final_kernel re-zeroes it after reading, so no separate
// zeroing kernel is needed (graph capture does not execute the kernels; the
// correctness run and every replay each restore the invariant).
// ---------------------------------------------------------------------------

#define HID 16
#define ACC_STRIDE 18
#define MAX_GRAPHS 4096

__device__ float g_acc[MAX_GRAPHS * ACC_STRIDE];   // zero-initialized

// ---------------------------------------------------------------------------
// One warp processes a contiguous, 4-aligned chunk of node rows. batch[] is
// sorted; if batch[start] == batch[end-1] the whole chunk is one graph and we
// run a branch-free unroll-by-4 streaming loop (no batch loads at all).
// Otherwise we fall back to the per-element boundary-tracking loop.
//
// Lane l loads float4 l of the 128-float row -> coalesced 512B per warp-node.
// Lanes 0..15 own one component of the r accumulator.
// ---------------------------------------------------------------------------
__global__ __launch_bounds__(256) void accum_kernel(
    const float4* __restrict__ x4,      // [N, 32] float4 view of x[N,128]
    const float*  __restrict__ clockp,  // [N]
    const int*    __restrict__ batch,   // [N] sorted
    const float4* __restrict__ Wb4,     // [32] float4 view of W_base[128]
    const float*  __restrict__ W1,      // [16]
    const float*  __restrict__ b1,      // [16]
    int N, int chunk)                   // chunk % 4 == 0
{
    const int lane = threadIdx.x & 31;
    const int gwid = (blockIdx.x * blockDim.x + threadIdx.x) >> 5;

    int start = gwid * chunk;
    if (start >= N) return;
    int end = start + chunk;
    if (end > N) end = N;

    const float4 wb = Wb4[lane];
    float w1l = 0.0f, b1l = -1.0f;
    if (lane < HID) { w1l = W1[lane]; b1l = b1[lane]; }

    const int gfirst = batch[start];
    const int glast  = batch[end - 1];

    if (gfirst == glast) {
        // ---------------- fast path: single graph, branch-free ----------------
        float ax = 0.0f, ay = 0.0f, az = 0.0f, aw = 0.0f;
        float r0 = 0.0f, r1 = 0.0f;

        const float4* cl4 = (const float4*)clockp;
        int n = start;
        int nend4 = start + ((end - start) & ~3);   // start % 4 == 0

        for (; n < nend4; n += 4) {
            // front-batched independent streaming loads (MLP_p1 >= 5)
            const float4 xv0 = __ldcs(&x4[((n + 0) << 5) + lane]);
            const float4 xv1 = __ldcs(&x4[((n + 1) << 5) + lane]);
            const float4 xv2 = __ldcs(&x4[((n + 2) << 5) + lane]);
            const float4 xv3 = __ldcs(&x4[((n + 3) << 5) + lane]);
            const float4 cv  = cl4[n >> 2];          // broadcast, one line

            ax = fmaf(xv0.x, wb.x, ax); ay = fmaf(xv0.y, wb.y, ay);
            az = fmaf(xv0.z, wb.z, az); aw = fmaf(xv0.w, wb.w, aw);
            ax = fmaf(xv1.x, wb.x, ax); ay = fmaf(xv1.y, wb.y, ay);
            az = fmaf(xv1.z, wb.z, az); aw = fmaf(xv1.w, wb.w, aw);
            ax = fmaf(xv2.x, wb.x, ax); ay = fmaf(xv2.y, wb.y, ay);
            az = fmaf(xv2.z, wb.z, az); aw = fmaf(xv2.w, wb.w, aw);
            ax = fmaf(xv3.x, wb.x, ax); ay = fmaf(xv3.y, wb.y, ay);
            az = fmaf(xv3.z, wb.z, az); aw = fmaf(xv3.w, wb.w, aw);

            r0 += fmaxf(fmaf(cv.x, w1l, b1l), 0.0f);
            r1 += fmaxf(fmaf(cv.y, w1l, b1l), 0.0f);
            r0 += fmaxf(fmaf(cv.z, w1l, b1l), 0.0f);
            r1 += fmaxf(fmaf(cv.w, w1l, b1l), 0.0f);
        }
        for (; n < end; ++n) {                       // scalar tail (last warp)
            const float4 xv = __ldcs(&x4[(n << 5) + lane]);
            const float  c  = clockp[n];
            ax = fmaf(xv.x, wb.x, ax); ay = fmaf(xv.y, wb.y, ay);
            az = fmaf(xv.z, wb.z, az); aw = fmaf(xv.w, wb.w, aw);
            r0 += fmaxf(fmaf(c, w1l, b1l), 0.0f);
        }

        float s = (ax + ay) + (az + aw);
        #pragma unroll
        for (int off = 16; off; off >>= 1)
            s += __shfl_xor_sync(0xffffffffu, s, off);

        const float racc = r0 + r1;
        const float cnt  = (float)(end - start);
        if (lane < HID)          atomicAdd(&g_acc[gfirst * ACC_STRIDE + lane], racc);
        else if (lane == HID)    atomicAdd(&g_acc[gfirst * ACC_STRIDE + 16],  s);
        else if (lane == HID+1)  atomicAdd(&g_acc[gfirst * ACC_STRIDE + 17],  cnt);
        return;
    }

    // ---------------- general path: chunk crosses graph boundary ----------------
    int   cur   = gfirst;
    float pacc0 = 0.0f, pacc1 = 0.0f;
    float racc  = 0.0f;
    float cnt   = 0.0f;

    for (int n = start; n < end; ++n) {
        const float4 xv = __ldcs(&x4[(n << 5) + lane]);
        const int    g  = batch[n];
        const float  c  = clockp[n];

        if (g != cur) {
            float s = pacc0 + pacc1;
            #pragma unroll
            for (int off = 16; off; off >>= 1)
                s += __shfl_xor_sync(0xffffffffu, s, off);
            if (lane < HID)         atomicAdd(&g_acc[cur * ACC_STRIDE + lane], racc);
            else if (lane == HID)   atomicAdd(&g_acc[cur * ACC_STRIDE + 16],  s);
            else if (lane == HID+1) atomicAdd(&g_acc[cur * ACC_STRIDE + 17],  cnt);
            pacc0 = 0.0f; pacc1 = 0.0f; racc = 0.0f; cnt = 0.0f;
            cur = g;
        }

        pacc0 = fmaf(xv.x, wb.x, pacc0);
        pacc1 = fmaf(xv.y, wb.y, pacc1);
        pacc0 = fmaf(xv.z, wb.z, pacc0);
        pacc1 = fmaf(xv.w, wb.w, pacc1);
        racc += fmaxf(fmaf(c, w1l, b1l), 0.0f);
        cnt  += 1.0f;
    }

    {
        float s = pacc0 + pacc1;
        #pragma unroll
        for (int off = 16; off; off >>= 1)
            s += __shfl_xor_sync(0xffffffffu, s, off);
        if (lane < HID)         atomicAdd(&g_acc[cur * ACC_STRIDE + lane], racc);
        else if (lane == HID)   atomicAdd(&g_acc[cur * ACC_STRIDE + 16],  s);
        else if (lane == HID+1) atomicAdd(&g_acc[cur * ACC_STRIDE + 17],  cnt);
    }
}

// ---------------------------------------------------------------------------
// Final per-graph MLP. One thread per graph. After reading its accumulators,
// each thread re-zeroes them, restoring the "acc is zero on entry" invariant
// for the next kernel_launch call / graph replay.
// ---------------------------------------------------------------------------
__global__ __launch_bounds__(256) void final_kernel(
    const float* __restrict__ b_base,   // [1]
    const float* __restrict__ W2,       // [16,16] row-major
    const float* __restrict__ b2,       // [16]
    const float* __restrict__ W3,       // [17,32] row-major
    const float* __restrict__ b3,       // [32]
    const float* __restrict__ W4,       // [32]
    const float* __restrict__ b4,       // [1]
    float* __restrict__ out,            // [B]
    int B)
{
    int g = blockIdx.x * blockDim.x + threadIdx.x;
    if (g >= B) return;

    float* a = &g_acc[g * ACC_STRIDE];
    float acc[ACC_STRIDE];
    #pragma unroll
    for (int i = 0; i < ACC_STRIDE; ++i) { acc[i] = a[i]; a[i] = 0.0f; }

    float cnt = acc[17];
    float inv = 1.0f / fmaxf(cnt, 1.0f);

    float combined[HID + 1];
    combined[0] = acc[16] * inv + b_base[0];

    float mr[HID];
    #pragma unroll
    for (int i = 0; i < HID; ++i) mr[i] = acc[i] * inv;

    #pragma unroll
    for (int j = 0; j < HID; ++j) {
        float v = b2[j];
        #pragma unroll
        for (int i = 0; i < HID; ++i)
            v = fmaf(mr[i], W2[i * HID + j], v);
        combined[1 + j] = v;
    }

    float o = b4[0];
    #pragma unroll
    for (int k = 0; k < 32; ++k) {
        float h = b3[k];
        #pragma unroll
        for (int t = 0; t < HID + 1; ++t)
            h = fmaf(combined[t], W3[t * 32 + k], h);
        o = fmaf(fmaxf(h, 0.0f), W4[k], o);
    }
    out[g] = o;
}

// ---------------------------------------------------------------------------
extern "C" void kernel_launch(void* const* d_in, const int* in_sizes, int n_in,
                              void* d_out, int out_size)
{
    // metadata order: x, clock_period, batch, W_base, b_base, W1, b1, W2, b2,
    //                 W3, b3, W4, b4
    const float* x       = (const float*)d_in[0];
    const float* clockp  = (const float*)d_in[1];
    const int*   batch   = (const int*)  d_in[2];
    const float* W_base  = (const float*)d_in[3];
    const float* b_base  = (const float*)d_in[4];
    const float* W1      = (const float*)d_in[5];
    const float* b1      = (const float*)d_in[6];
    const float* W2      = (const float*)d_in[7];
    const float* b2      = (const float*)d_in[8];
    const float* W3      = (const float*)d_in[9];
    const float* b3      = (const float*)d_in[10];
    const float* W4      = (const float*)d_in[11];
    const float* b4      = (const float*)d_in[12];
    float*       out     = (float*)d_out;

    const int N = in_sizes[2];          // number of nodes
    const int B = out_size;             // number of graphs

    // streaming accumulation
    {
        const int BLK  = 256;
        const int GRID = 148 * 8;
        const int warps = GRID * (BLK / 32);
        int chunk = (N + warps - 1) / warps;
        chunk = (chunk + 3) & ~3;       // keep chunks 4-aligned for float4 clock loads
        accum_kernel<<<GRID, BLK>>>(
            (const float4*)x, clockp, batch, (const float4*)W_base,
            W1, b1, N, chunk);
    }

    // per-graph final MLP (+ accumulator re-zero)
    {
        int blk = 256;
        final_kernel<<<(B + blk - 1) / blk, blk>>>(
            b_base, W2, b2, W3, b3, W4, b4, out, B);
    }
}